// round 3
// baseline (speedup 1.0000x reference)
#include <cuda_runtime.h>
#include <math_constants.h>

// Problem shape (fixed for this bench instance)
#define NB   4      // batch
#define CIN  4
#define COUT 4
#define KS   5
#define PAD  2      // KS/2
#define HH   128
#define WW   128
#define HW   (HH*WW)

// Tiling
#define TW 32
#define TH 8
#define PW (TW + 2*PAD)   // 36
#define PH (TH + 2*PAD)   // 12

__device__ __forceinline__ float ex2_approx(float x) {
    float y;
    asm("ex2.approx.f32 %0, %1;" : "=f"(y) : "f"(x));
    return y;
}
__device__ __forceinline__ float lg2_approx(float x) {
    float y;
    asm("lg2.approx.f32 %0, %1;" : "=f"(y) : "f"(x));
    return y;
}

__global__ __launch_bounds__(256)
void prop_belief_kernel(const float* __restrict__ lb,
                        const float* __restrict__ lk,
                        float* __restrict__ out)
{
    __shared__ float sh[CIN][PH][PW];   // lb * log2e, -inf padded

    const int tx = threadIdx.x;               // 0..31
    const int ty = threadIdx.y;               // 0..7
    const int x0 = blockIdx.x * TW;
    const int y0 = blockIdx.y * TH;
    const int n    = blockIdx.z >> 2;         // blockIdx.z = n*COUT + cout
    const int cout = blockIdx.z & 3;

    const float LOG2E = 1.4426950408889634f;
    const float LN2   = 0.6931471805599453f;

    // ---- stage lb tile (pre-scaled by log2e), pad with -inf ----
    const int tid = ty * TW + tx;
    #pragma unroll
    for (int i = tid; i < CIN * PH * PW; i += 256) {
        const int cin = i / (PH * PW);
        const int rem = i - cin * (PH * PW);
        const int r = rem / PW;
        const int c = rem - r * PW;
        const int ys = y0 - PAD + r;
        const int xs = x0 - PAD + c;
        float v = -CUDART_INF_F;
        if (ys >= 0 && ys < HH && xs >= 0 && xs < WW)
            v = lb[((n * CIN + cin) * HH + ys) * WW + xs] * LOG2E;
        sh[cin][r][c] = v;
    }
    __syncthreads();

    const int yo = y0 + ty;
    const int xo = x0 + tx;

    // Base pointer for (n, cin=0, cout*KK) channel block of log_kernel.
    // lk layout: [N][CIN][COUT*KK][H][W]
    const float* lk0 = lk + ((size_t)(n * CIN) * (COUT * KS * KS)
                             + (size_t)cout * KS * KS) * HW;

    float s0 = 0.f, s1 = 0.f, s2 = 0.f, s3 = 0.f;

    #pragma unroll
    for (int ky = 0; ky < KS; ky++) {
        const int ys  = yo + PAD - ky;
        const int ysc = min(max(ys, 0), HH - 1);       // clamped address only
        const int yl  = ty + 2 * PAD - ky;             // shared row (holds -inf if OOB)
        #pragma unroll
        for (int kx = 0; kx < KS; kx++) {
            const int xs  = xo + PAD - kx;
            const int xsc = min(max(xs, 0), WW - 1);
            const int xl  = tx + 2 * PAD - kx;
            const int off = ysc * WW + xsc;
            const int k   = ky * KS + kx;
            // 4 independent accumulators (one per cin) -> 4 FADD chains
            {
                const float v  = lk0[(size_t)(0 * (COUT*KS*KS) + k) * HW + off];
                s0 += ex2_approx(fmaf(v, LOG2E, sh[0][yl][xl]));
            }
            {
                const float v  = lk0[(size_t)(1 * (COUT*KS*KS) + k) * HW + off];
                s1 += ex2_approx(fmaf(v, LOG2E, sh[1][yl][xl]));
            }
            {
                const float v  = lk0[(size_t)(2 * (COUT*KS*KS) + k) * HW + off];
                s2 += ex2_approx(fmaf(v, LOG2E, sh[2][yl][xl]));
            }
            {
                const float v  = lk0[(size_t)(3 * (COUT*KS*KS) + k) * HW + off];
                s3 += ex2_approx(fmaf(v, LOG2E, sh[3][yl][xl]));
            }
        }
    }

    const float s = (s0 + s1) + (s2 + s3);
    out[((n * COUT + cout) * HH + yo) * WW + xo] = lg2_approx(s) * LN2;
}

extern "C" void kernel_launch(void* const* d_in, const int* in_sizes, int n_in,
                              void* d_out, int out_size)
{
    const float* lb = (const float*)d_in[0];   // (4,4,128,128)
    const float* lk = (const float*)d_in[1];   // (4,4,100,128,128)
    float* out = (float*)d_out;                // (4,4,128,128)

    dim3 block(TW, TH);                        // 256 threads
    dim3 grid(WW / TW, HH / TH, NB * COUT);    // (4, 16, 16)
    prop_belief_kernel<<<grid, block>>>(lb, lk, out);
}